// round 12
// baseline (speedup 1.0000x reference)
#include <cuda_runtime.h>
#include <cuda_bf16.h>
#include <math.h>
#include <stdint.h>

#define BB 2048
#define TT 80
#define LL 128
#define MT 16             // batch rows per CTA
#define NCF 128           // grid
#define SVS 136           // padded V row stride in bf16 elems

// ---- helpers ----
__device__ __forceinline__ uint32_t packbf2(float lo, float hi) {
    uint32_t r;
    asm("cvt.rn.satfinite.bf16x2.f32 %0, %1, %2;" : "=r"(r) : "f"(hi), "f"(lo));
    return r;
}
__device__ __forceinline__ uint32_t smem_u32(const void* p) {
    uint32_t a;
    asm("{ .reg .u64 t; cvta.to.shared.u64 t, %1; cvt.u32.u64 %0, t; }" : "=r"(a) : "l"(p));
    return a;
}
__device__ __forceinline__ void ldsm4(uint32_t r[4], uint32_t addr) {
    asm volatile("ldmatrix.sync.aligned.m8n8.x4.shared.b16 {%0,%1,%2,%3}, [%4];"
        : "=r"(r[0]), "=r"(r[1]), "=r"(r[2]), "=r"(r[3]) : "r"(addr));
}
__device__ __forceinline__ void mma16816(float d[4], const uint32_t a[4], const uint32_t b[2]) {
    asm volatile("mma.sync.aligned.m16n8k16.row.col.f32.bf16.bf16.f32 "
        "{%0,%1,%2,%3}, {%4,%5,%6,%7}, {%8,%9}, {%0,%1,%2,%3};"
        : "+f"(d[0]), "+f"(d[1]), "+f"(d[2]), "+f"(d[3])
        : "r"(a[0]), "r"(a[1]), "r"(a[2]), "r"(a[3]), "r"(b[0]), "r"(b[1]));
}

// -------------------------------------------------------------------------
// Fused CRF kernel (R8 structure). 128 CTAs x 256 thr (8 warps), 1 CTA/SM.
// Warp w owns n-slice [16w,16w+16). B = exp(trans) in regs.
// R12 deltas vs R8 (register-neutral only):
//   - fragment identity: own-k-tile A-frag kept in AfOwn (the STS payload
//     regs), saving 1 of 8 ldsm per warp per step
//   - __logf / __fdividef fast paths
// -------------------------------------------------------------------------
__global__ void __launch_bounds__(256, 1) crf_fwd_kernel(
    const float* __restrict__ x,
    const float* __restrict__ trans,
    const float* __restrict__ st,
    const float* __restrict__ et,
    const int*   __restrict__ y,
    float*       __restrict__ out)
{
    __shared__ __align__(16) __nv_bfloat16 sV[2][MT * SVS];
    __shared__ float sSt[LL];
    __shared__ float sRed[8][MT];
    __shared__ float sS[MT];
    __shared__ float sNum[MT][16];

    const int tid  = threadIdx.x;
    const int w    = tid >> 5;
    const int lane = tid & 31;
    const int gb   = blockIdx.x * MT;

    // ---- static B fragments: exp(trans)[k][n] in mma col-B layout ----
    uint32_t Bf[8][2][2];
    {
        const int jn = 16 * w + (lane >> 2);
        const int kb = (lane & 3) * 2;
        #pragma unroll
        for (int ks = 0; ks < 8; ks++)
            #pragma unroll
            for (int nt = 0; nt < 2; nt++) {
                int j  = jn + nt * 8;
                int k0 = ks * 16 + kb;
                Bf[ks][nt][0] = packbf2(__expf(trans[k0 * LL + j]),
                                        __expf(trans[(k0 + 1) * LL + j]));
                Bf[ks][nt][1] = packbf2(__expf(trans[(k0 + 8) * LL + j]),
                                        __expf(trans[(k0 + 9) * LL + j]));
            }
    }
    const int rQ  = lane >> 2;
    const int cQ2 = (lane & 3) * 2;
    const int c0  = 16 * w + cQ2;
    float eet[2][2];
    eet[0][0] = __expf(et[c0]);     eet[0][1] = __expf(et[c0 + 1]);
    eet[1][0] = __expf(et[c0 + 8]); eet[1][1] = __expf(et[c0 + 9]);
    if (tid < LL) sSt[tid] = st[tid];
    if (tid < MT) sS[tid] = 0.0f;

    // ---- gold-path numerator: 16 threads per row, 5 time-chunks each ----
    {
        const int nrow = tid >> 4, nsub = tid & 15;
        const int*   yr = y + (gb + nrow) * TT;
        const float* xn = x + (size_t)(gb + nrow) * TT * LL;
        float nacc = 0.0f;
        #pragma unroll
        for (int k = 0; k < 5; k++) {
            int t = nsub + 16 * k;
            int cur = yr[t];
            nacc += xn[t * LL + cur];
            if (t < TT - 1) nacc += trans[cur * LL + yr[t + 1]];
        }
        if (nsub == 0)  nacc += st[yr[0]];
        if (nsub == 15) nacc += et[yr[TT - 1]];
        sNum[nrow][nsub] = nacc;
    }
    __syncthreads();

    // ---- t = 0 init: V0 = exp(st + x0), staged 16 thr/row x 8 cols ----
    {
        const int prow = tid >> 4;
        const int pc   = (tid & 15) * 8;
        const float* xr = x + ((size_t)(gb + prow) * TT) * LL + pc;
        float4 a = *(const float4*)(xr);
        float4 b = *(const float4*)(xr + 4);
        uint4 v;
        v.x = packbf2(__expf(sSt[pc + 0] + a.x), __expf(sSt[pc + 1] + a.y));
        v.y = packbf2(__expf(sSt[pc + 2] + a.z), __expf(sSt[pc + 3] + a.w));
        v.z = packbf2(__expf(sSt[pc + 4] + b.x), __expf(sSt[pc + 5] + b.y));
        v.w = packbf2(__expf(sSt[pc + 6] + b.z), __expf(sSt[pc + 7] + b.w));
        *(uint4*)&sV[0][prow * SVS + pc] = v;
    }

    // ---- emission prefetch pointers (fragment coords, 2 steps ahead) ----
    const float* xrA = x + ((size_t)(gb + rQ)     * TT) * LL + c0;
    const float* xrB = x + ((size_t)(gb + rQ + 8) * TT) * LL + c0;
    float2 xpf[2][4];   // [t&1][h*2+nt]
    #pragma unroll
    for (int nt = 0; nt < 2; nt++) {
        xpf[1][0 + nt] = *(const float2*)(xrA + LL + nt * 8);
        xpf[1][2 + nt] = *(const float2*)(xrB + LL + nt * 8);
        xpf[0][0 + nt] = *(const float2*)(xrA + 2 * LL + nt * 8);
        xpf[0][2 + nt] = *(const float2*)(xrB + 2 * LL + nt * 8);
    }

    // ---- per-lane ldmatrix / STS offsets (bytes) ----
    const int rowL = lane & 15;
    const int sel8 = (lane >> 4) * 8;
    const uint32_t Aoff = (rowL * SVS + sel8) * 2;
    uint32_t Voff[2];
    #pragma unroll
    for (int h = 0; h < 2; h++)
        Voff[h] = ((h * 8 + rQ) * SVS + 16 * w + cQ2) * 2;

    const uint32_t svb[2] = { smem_u32(&sV[0][0]), smem_u32(&sV[1][0]) };

    float val[2][4];
    uint32_t AfOwn[4];   // own k-tile A-frag == previous STS payload

    for (int t = 1; t < TT; t++) {
        const int rd = (t - 1) & 1, wr = t & 1;
        const int b  = t & 1;
        __syncthreads();

        // A fragments: 7 via ldsm; own k-tile from kept regs (t >= 2)
        uint32_t Af[8][4];
        #pragma unroll
        for (int ks = 0; ks < 8; ks++)
            if (ks != w) ldsm4(Af[ks], svb[rd] + Aoff + ks * 32);
        if (t == 1) {
            ldsm4(Af[w], svb[rd] + Aoff + w * 32);
        } else {
            Af[w][0] = AfOwn[0]; Af[w][1] = AfOwn[1];
            Af[w][2] = AfOwn[2]; Af[w][3] = AfOwn[3];
        }

        // emissions for this step from prefetch buffer
        float P[2][4];
        #pragma unroll
        for (int h = 0; h < 2; h++)
            #pragma unroll
            for (int nt = 0; nt < 2; nt++) {
                float2 xv = xpf[b][h * 2 + nt];
                P[nt][2 * h]     = __expf(xv.x);
                P[nt][2 * h + 1] = __expf(xv.y);
            }
        // refill buffer for t+2
        if (t + 2 < TT) {
            #pragma unroll
            for (int nt = 0; nt < 2; nt++) {
                xpf[b][0 + nt] = *(const float2*)(xrA + (size_t)(t + 2) * LL + nt * 8);
                xpf[b][2 + nt] = *(const float2*)(xrB + (size_t)(t + 2) * LL + nt * 8);
            }
        }

        // split-K GEMM
        float D0[2][4] = {{0.f,0.f,0.f,0.f},{0.f,0.f,0.f,0.f}};
        float D1[2][4] = {{0.f,0.f,0.f,0.f},{0.f,0.f,0.f,0.f}};
        #pragma unroll
        for (int ks = 0; ks < 4; ks++) {
            mma16816(D0[0], Af[ks],     Bf[ks][0]);
            mma16816(D0[1], Af[ks],     Bf[ks][1]);
            mma16816(D1[0], Af[ks + 4], Bf[ks + 4][0]);
            mma16816(D1[1], Af[ks + 4], Bf[ks + 4][1]);
        }
        #pragma unroll
        for (int nt = 0; nt < 2; nt++)
            #pragma unroll
            for (int k = 0; k < 4; k++)
                val[nt][k] = (D0[nt][k] + D1[nt][k]) * P[nt][k];

        // per-row renorm every 8 steps (same scheme as R8)
        if ((t & 7) == 0) {
            #pragma unroll
            for (int h = 0; h < 2; h++) {
                float m = fmaxf(fmaxf(val[0][2*h], val[0][2*h+1]),
                                fmaxf(val[1][2*h], val[1][2*h+1]));
                m = fmaxf(m, __shfl_xor_sync(0xffffffffu, m, 1));
                m = fmaxf(m, __shfl_xor_sync(0xffffffffu, m, 2));
                if ((lane & 3) == 0) sRed[w][h * 8 + rQ] = m;
            }
            __syncthreads();
            #pragma unroll
            for (int h = 0; h < 2; h++) {
                int row = h * 8 + rQ;
                float m = sRed[0][row];
                #pragma unroll
                for (int w2 = 1; w2 < 8; w2++) m = fmaxf(m, sRed[w2][row]);
                float inv = __fdividef(1.0f, m);
                val[0][2*h] *= inv; val[0][2*h+1] *= inv;
                val[1][2*h] *= inv; val[1][2*h+1] *= inv;
                if (w == 0 && (lane & 3) == 0) sS[row] += __logf(m);
            }
        }

        // pack once: STS payload AND next step's own A-frag
        AfOwn[0] = packbf2(val[0][0], val[0][1]);
        AfOwn[1] = packbf2(val[0][2], val[0][3]);
        AfOwn[2] = packbf2(val[1][0], val[1][1]);
        AfOwn[3] = packbf2(val[1][2], val[1][3]);

        if (t < TT - 1) {
            char* vb = (char*)&sV[wr][0];
            *(uint32_t*)(vb + Voff[0])      = AfOwn[0];
            *(uint32_t*)(vb + Voff[1])      = AfOwn[1];
            *(uint32_t*)(vb + Voff[0] + 16) = AfOwn[2];
            *(uint32_t*)(vb + Voff[1] + 16) = AfOwn[3];
        }
    }

    // ---- epilogue: Z per row, then out = num - (slog + log Z) ----
    #pragma unroll
    for (int h = 0; h < 2; h++) {
        float z = val[0][2*h] * eet[0][0] + val[0][2*h+1] * eet[0][1]
                + val[1][2*h] * eet[1][0] + val[1][2*h+1] * eet[1][1];
        z += __shfl_xor_sync(0xffffffffu, z, 1);
        z += __shfl_xor_sync(0xffffffffu, z, 2);
        if ((lane & 3) == 0) sRed[w][h * 8 + rQ] = z;
    }
    __syncthreads();
    if (tid < MT) {
        float Z = 0.0f;
        #pragma unroll
        for (int w2 = 0; w2 < 8; w2++) Z += sRed[w2][tid];
        float num = 0.0f;
        #pragma unroll
        for (int k = 0; k < 16; k++) num += sNum[tid][k];
        out[gb + tid] = num - (sS[tid] + __logf(Z));
    }
}

// -------------------------------------------------------------------------
extern "C" void kernel_launch(void* const* d_in, const int* in_sizes, int n_in,
                              void* d_out, int out_size)
{
    const float* x     = (const float*)d_in[0];
    const float* trans = (const float*)d_in[1];
    const float* st    = (const float*)d_in[2];
    const float* et    = (const float*)d_in[3];
    const int*   y     = (const int*)  d_in[4];
    float*       out   = (float*)d_out;

    crf_fwd_kernel<<<NCF, 256>>>(x, trans, st, et, y, out);
}

// round 13
// speedup vs baseline: 1.8772x; 1.8772x over previous
#include <cuda_runtime.h>
#include <cuda_bf16.h>
#include <math.h>
#include <stdint.h>

#define BB 2048
#define TT 80
#define LL 128
#define MT 16             // batch rows per CTA
#define NCF 128           // grid
#define SVS 136           // padded V row stride in bf16 elems

// ---- helpers ----
__device__ __forceinline__ uint32_t packbf2(float lo, float hi) {
    uint32_t r;
    asm("cvt.rn.satfinite.bf16x2.f32 %0, %1, %2;" : "=r"(r) : "f"(hi), "f"(lo));
    return r;
}
__device__ __forceinline__ uint32_t smem_u32(const void* p) {
    uint32_t a;
    asm("{ .reg .u64 t; cvta.to.shared.u64 t, %1; cvt.u32.u64 %0, t; }" : "=r"(a) : "l"(p));
    return a;
}
__device__ __forceinline__ void ldsm4(uint32_t r[4], uint32_t addr) {
    asm volatile("ldmatrix.sync.aligned.m8n8.x4.shared.b16 {%0,%1,%2,%3}, [%4];"
        : "=r"(r[0]), "=r"(r[1]), "=r"(r[2]), "=r"(r[3]) : "r"(addr));
}
__device__ __forceinline__ void mma16816(float d[4], const uint32_t a[4], const uint32_t b[2]) {
    asm volatile("mma.sync.aligned.m16n8k16.row.col.f32.bf16.bf16.f32 "
        "{%0,%1,%2,%3}, {%4,%5,%6,%7}, {%8,%9}, {%0,%1,%2,%3};"
        : "+f"(d[0]), "+f"(d[1]), "+f"(d[2]), "+f"(d[3])
        : "r"(a[0]), "r"(a[1]), "r"(a[2]), "r"(a[3]), "r"(b[0]), "r"(b[1]));
}

// -------------------------------------------------------------------------
// Fused CRF kernel (R8 structure). 128 CTAs x 256 thr (8 warps), 1 CTA/SM.
// Warp w owns n-slice [16w,16w+16). B = exp(trans) in regs.
// R13 deltas vs R8 (STATIC indexing only — R11/R12 regressed because
// Af[w] dynamic indexing demoted the fragment array to local memory):
//   - fragment identity via fully-unrolled static-index predicated loop
//   - __logf / __fdividef fast paths
// -------------------------------------------------------------------------
__global__ void __launch_bounds__(256, 1) crf_fwd_kernel(
    const float* __restrict__ x,
    const float* __restrict__ trans,
    const float* __restrict__ st,
    const float* __restrict__ et,
    const int*   __restrict__ y,
    float*       __restrict__ out)
{
    __shared__ __align__(16) __nv_bfloat16 sV[2][MT * SVS];
    __shared__ float sSt[LL];
    __shared__ float sRed[8][MT];
    __shared__ float sS[MT];
    __shared__ float sNum[MT][16];

    const int tid  = threadIdx.x;
    const int w    = tid >> 5;
    const int lane = tid & 31;
    const int gb   = blockIdx.x * MT;

    // ---- static B fragments: exp(trans)[k][n] in mma col-B layout ----
    uint32_t Bf[8][2][2];
    {
        const int jn = 16 * w + (lane >> 2);
        const int kb = (lane & 3) * 2;
        #pragma unroll
        for (int ks = 0; ks < 8; ks++)
            #pragma unroll
            for (int nt = 0; nt < 2; nt++) {
                int j  = jn + nt * 8;
                int k0 = ks * 16 + kb;
                Bf[ks][nt][0] = packbf2(__expf(trans[k0 * LL + j]),
                                        __expf(trans[(k0 + 1) * LL + j]));
                Bf[ks][nt][1] = packbf2(__expf(trans[(k0 + 8) * LL + j]),
                                        __expf(trans[(k0 + 9) * LL + j]));
            }
    }
    const int rQ  = lane >> 2;
    const int cQ2 = (lane & 3) * 2;
    const int c0  = 16 * w + cQ2;
    float eet[2][2];
    eet[0][0] = __expf(et[c0]);     eet[0][1] = __expf(et[c0 + 1]);
    eet[1][0] = __expf(et[c0 + 8]); eet[1][1] = __expf(et[c0 + 9]);
    if (tid < LL) sSt[tid] = st[tid];
    if (tid < MT) sS[tid] = 0.0f;

    // ---- gold-path numerator: 16 threads per row, 5 time-chunks each ----
    {
        const int nrow = tid >> 4, nsub = tid & 15;
        const int*   yr = y + (gb + nrow) * TT;
        const float* xn = x + (size_t)(gb + nrow) * TT * LL;
        float nacc = 0.0f;
        #pragma unroll
        for (int k = 0; k < 5; k++) {
            int t = nsub + 16 * k;
            int cur = yr[t];
            nacc += xn[t * LL + cur];
            if (t < TT - 1) nacc += trans[cur * LL + yr[t + 1]];
        }
        if (nsub == 0)  nacc += st[yr[0]];
        if (nsub == 15) nacc += et[yr[TT - 1]];
        sNum[nrow][nsub] = nacc;
    }
    __syncthreads();

    // ---- t = 0 init: V0 = exp(st + x0), staged 16 thr/row x 8 cols ----
    {
        const int prow = tid >> 4;
        const int pc   = (tid & 15) * 8;
        const float* xr = x + ((size_t)(gb + prow) * TT) * LL + pc;
        float4 a = *(const float4*)(xr);
        float4 b = *(const float4*)(xr + 4);
        uint4 v;
        v.x = packbf2(__expf(sSt[pc + 0] + a.x), __expf(sSt[pc + 1] + a.y));
        v.y = packbf2(__expf(sSt[pc + 2] + a.z), __expf(sSt[pc + 3] + a.w));
        v.z = packbf2(__expf(sSt[pc + 4] + b.x), __expf(sSt[pc + 5] + b.y));
        v.w = packbf2(__expf(sSt[pc + 6] + b.z), __expf(sSt[pc + 7] + b.w));
        *(uint4*)&sV[0][prow * SVS + pc] = v;
    }

    // ---- emission prefetch pointers (fragment coords, 2 steps ahead) ----
    const float* xrA = x + ((size_t)(gb + rQ)     * TT) * LL + c0;
    const float* xrB = x + ((size_t)(gb + rQ + 8) * TT) * LL + c0;
    float2 xpf[2][4];   // [t&1][h*2+nt]
    #pragma unroll
    for (int nt = 0; nt < 2; nt++) {
        xpf[1][0 + nt] = *(const float2*)(xrA + LL + nt * 8);
        xpf[1][2 + nt] = *(const float2*)(xrB + LL + nt * 8);
        xpf[0][0 + nt] = *(const float2*)(xrA + 2 * LL + nt * 8);
        xpf[0][2 + nt] = *(const float2*)(xrB + 2 * LL + nt * 8);
    }

    // ---- per-lane ldmatrix / STS offsets (bytes) ----
    const int rowL = lane & 15;
    const int sel8 = (lane >> 4) * 8;
    const uint32_t Aoff = (rowL * SVS + sel8) * 2;
    uint32_t Voff[2];
    #pragma unroll
    for (int h = 0; h < 2; h++)
        Voff[h] = ((h * 8 + rQ) * SVS + 16 * w + cQ2) * 2;

    const uint32_t svb[2] = { smem_u32(&sV[0][0]), smem_u32(&sV[1][0]) };

    float val[2][4];
    uint32_t AfOwn[4];   // own k-tile A-frag == previous STS payload

    for (int t = 1; t < TT; t++) {
        const int rd = (t - 1) & 1, wr = t & 1;
        const int b  = t & 1;
        const bool reuse = (t > 1);
        __syncthreads();

        // A fragments: all indices STATIC; own k-tile (ks == w) reused
        // from registers for t >= 2 (uniform predicate, no dynamic index).
        uint32_t Af[8][4];
        #pragma unroll
        for (int ks = 0; ks < 8; ks++) {
            if (!(reuse && ks == w))
                ldsm4(Af[ks], svb[rd] + Aoff + ks * 32);
        }
        #pragma unroll
        for (int ks = 0; ks < 8; ks++) {
            if (reuse && ks == w) {
                Af[ks][0] = AfOwn[0]; Af[ks][1] = AfOwn[1];
                Af[ks][2] = AfOwn[2]; Af[ks][3] = AfOwn[3];
            }
        }

        // emissions for this step from prefetch buffer
        float P[2][4];
        #pragma unroll
        for (int h = 0; h < 2; h++)
            #pragma unroll
            for (int nt = 0; nt < 2; nt++) {
                float2 xv = xpf[b][h * 2 + nt];
                P[nt][2 * h]     = __expf(xv.x);
                P[nt][2 * h + 1] = __expf(xv.y);
            }
        // refill buffer for t+2
        if (t + 2 < TT) {
            #pragma unroll
            for (int nt = 0; nt < 2; nt++) {
                xpf[b][0 + nt] = *(const float2*)(xrA + (size_t)(t + 2) * LL + nt * 8);
                xpf[b][2 + nt] = *(const float2*)(xrB + (size_t)(t + 2) * LL + nt * 8);
            }
        }

        // split-K GEMM
        float D0[2][4] = {{0.f,0.f,0.f,0.f},{0.f,0.f,0.f,0.f}};
        float D1[2][4] = {{0.f,0.f,0.f,0.f},{0.f,0.f,0.f,0.f}};
        #pragma unroll
        for (int ks = 0; ks < 4; ks++) {
            mma16816(D0[0], Af[ks],     Bf[ks][0]);
            mma16816(D0[1], Af[ks],     Bf[ks][1]);
            mma16816(D1[0], Af[ks + 4], Bf[ks + 4][0]);
            mma16816(D1[1], Af[ks + 4], Bf[ks + 4][1]);
        }
        #pragma unroll
        for (int nt = 0; nt < 2; nt++)
            #pragma unroll
            for (int k = 0; k < 4; k++)
                val[nt][k] = (D0[nt][k] + D1[nt][k]) * P[nt][k];

        // per-row renorm every 8 steps (same scheme as R8)
        if ((t & 7) == 0) {
            #pragma unroll
            for (int h = 0; h < 2; h++) {
                float m = fmaxf(fmaxf(val[0][2*h], val[0][2*h+1]),
                                fmaxf(val[1][2*h], val[1][2*h+1]));
                m = fmaxf(m, __shfl_xor_sync(0xffffffffu, m, 1));
                m = fmaxf(m, __shfl_xor_sync(0xffffffffu, m, 2));
                if ((lane & 3) == 0) sRed[w][h * 8 + rQ] = m;
            }
            __syncthreads();
            #pragma unroll
            for (int h = 0; h < 2; h++) {
                int row = h * 8 + rQ;
                float m = sRed[0][row];
                #pragma unroll
                for (int w2 = 1; w2 < 8; w2++) m = fmaxf(m, sRed[w2][row]);
                float inv = __fdividef(1.0f, m);
                val[0][2*h] *= inv; val[0][2*h+1] *= inv;
                val[1][2*h] *= inv; val[1][2*h+1] *= inv;
                if (w == 0 && (lane & 3) == 0) sS[row] += __logf(m);
            }
        }

        // pack once: STS payload AND next step's own A-frag
        AfOwn[0] = packbf2(val[0][0], val[0][1]);
        AfOwn[1] = packbf2(val[0][2], val[0][3]);
        AfOwn[2] = packbf2(val[1][0], val[1][1]);
        AfOwn[3] = packbf2(val[1][2], val[1][3]);

        if (t < TT - 1) {
            char* vb = (char*)&sV[wr][0];
            *(uint32_t*)(vb + Voff[0])      = AfOwn[0];
            *(uint32_t*)(vb + Voff[1])      = AfOwn[1];
            *(uint32_t*)(vb + Voff[0] + 16) = AfOwn[2];
            *(uint32_t*)(vb + Voff[1] + 16) = AfOwn[3];
        }
    }

    // ---- epilogue: Z per row, then out = num - (slog + log Z) ----
    #pragma unroll
    for (int h = 0; h < 2; h++) {
        float z = val[0][2*h] * eet[0][0] + val[0][2*h+1] * eet[0][1]
                + val[1][2*h] * eet[1][0] + val[1][2*h+1] * eet[1][1];
        z += __shfl_xor_sync(0xffffffffu, z, 1);
        z += __shfl_xor_sync(0xffffffffu, z, 2);
        if ((lane & 3) == 0) sRed[w][h * 8 + rQ] = z;
    }
    __syncthreads();
    if (tid < MT) {
        float Z = 0.0f;
        #pragma unroll
        for (int w2 = 0; w2 < 8; w2++) Z += sRed[w2][tid];
        float num = 0.0f;
        #pragma unroll
        for (int k = 0; k < 16; k++) num += sNum[tid][k];
        out[gb + tid] = num - (sS[tid] + __logf(Z));
    }
}

// -------------------------------------------------------------------------
extern "C" void kernel_launch(void* const* d_in, const int* in_sizes, int n_in,
                              void* d_out, int out_size)
{
    const float* x     = (const float*)d_in[0];
    const float* trans = (const float*)d_in[1];
    const float* st    = (const float*)d_in[2];
    const float* et    = (const float*)d_in[3];
    const int*   y     = (const int*)  d_in[4];
    float*       out   = (float*)d_out;

    crf_fwd_kernel<<<NCF, 256>>>(x, trans, st, et, y, out);
}

// round 15
// speedup vs baseline: 2.0557x; 1.0951x over previous
#include <cuda_runtime.h>
#include <cuda_bf16.h>
#include <math.h>
#include <stdint.h>

#define BB 2048
#define TT 80
#define LL 128
#define MT 16             // batch rows per CTA
#define NCF 128           // grid
#define SVS 136           // padded V row stride in bf16 elems

// ---- helpers ----
__device__ __forceinline__ uint32_t packbf2(float lo, float hi) {
    uint32_t r;
    asm("cvt.rn.satfinite.bf16x2.f32 %0, %1, %2;" : "=r"(r) : "f"(hi), "f"(lo));
    return r;
}
__device__ __forceinline__ uint32_t smem_u32(const void* p) {
    uint32_t a;
    asm("{ .reg .u64 t; cvta.to.shared.u64 t, %1; cvt.u32.u64 %0, t; }" : "=r"(a) : "l"(p));
    return a;
}
__device__ __forceinline__ void ldsm4(uint32_t r[4], uint32_t addr) {
    asm volatile("ldmatrix.sync.aligned.m8n8.x4.shared.b16 {%0,%1,%2,%3}, [%4];"
        : "=r"(r[0]), "=r"(r[1]), "=r"(r[2]), "=r"(r[3]) : "r"(addr));
}
__device__ __forceinline__ void mma16816(float d[4], const uint32_t a[4], const uint32_t b[2]) {
    asm volatile("mma.sync.aligned.m16n8k16.row.col.f32.bf16.bf16.f32 "
        "{%0,%1,%2,%3}, {%4,%5,%6,%7}, {%8,%9}, {%0,%1,%2,%3};"
        : "+f"(d[0]), "+f"(d[1]), "+f"(d[2]), "+f"(d[3])
        : "r"(a[0]), "r"(a[1]), "r"(a[2]), "r"(a[3]), "r"(b[0]), "r"(b[1]));
}

// -------------------------------------------------------------------------
// Fused CRF kernel — EXACT R8 structure (62.2 us baseline), single delta:
// logf -> __logf and 1/m -> __fdividef (scalar fast paths only; no control
// flow or register-allocation change). Fragment-identity abandoned after
// R11-R13 showed every form of it regresses (local-mem demotion / ALU).
// 128 CTAs x 256 thr (8 warps), 1 CTA/SM. Warp w owns n-slice
// [16w,16w+16). B = exp(trans) in regs. V double-buffered in SMEM via
// ldmatrix. Emissions LDG'd 2 steps ahead at fragment coords. Renorm
// every 8 steps. Numerator fused at kernel start.
// -------------------------------------------------------------------------
__global__ void __launch_bounds__(256, 1) crf_fwd_kernel(
    const float* __restrict__ x,
    const float* __restrict__ trans,
    const float* __restrict__ st,
    const float* __restrict__ et,
    const int*   __restrict__ y,
    float*       __restrict__ out)
{
    __shared__ __align__(16) __nv_bfloat16 sV[2][MT * SVS];
    __shared__ float sSt[LL];
    __shared__ float sRed[8][MT];
    __shared__ float sS[MT];
    __shared__ float sNum[MT][16];

    const int tid  = threadIdx.x;
    const int w    = tid >> 5;
    const int lane = tid & 31;
    const int gb   = blockIdx.x * MT;

    // ---- static B fragments: exp(trans)[k][n] in mma col-B layout ----
    uint32_t Bf[8][2][2];
    {
        const int jn = 16 * w + (lane >> 2);
        const int kb = (lane & 3) * 2;
        #pragma unroll
        for (int ks = 0; ks < 8; ks++)
            #pragma unroll
            for (int nt = 0; nt < 2; nt++) {
                int j  = jn + nt * 8;
                int k0 = ks * 16 + kb;
                Bf[ks][nt][0] = packbf2(__expf(trans[k0 * LL + j]),
                                        __expf(trans[(k0 + 1) * LL + j]));
                Bf[ks][nt][1] = packbf2(__expf(trans[(k0 + 8) * LL + j]),
                                        __expf(trans[(k0 + 9) * LL + j]));
            }
    }
    const int rQ  = lane >> 2;
    const int cQ2 = (lane & 3) * 2;
    const int c0  = 16 * w + cQ2;
    float eet[2][2];
    eet[0][0] = __expf(et[c0]);     eet[0][1] = __expf(et[c0 + 1]);
    eet[1][0] = __expf(et[c0 + 8]); eet[1][1] = __expf(et[c0 + 9]);
    if (tid < LL) sSt[tid] = st[tid];
    if (tid < MT) sS[tid] = 0.0f;

    // ---- gold-path numerator: 16 threads per row, 5 time-chunks each ----
    {
        const int nrow = tid >> 4, nsub = tid & 15;
        const int*   yr = y + (gb + nrow) * TT;
        const float* xn = x + (size_t)(gb + nrow) * TT * LL;
        float nacc = 0.0f;
        #pragma unroll
        for (int k = 0; k < 5; k++) {
            int t = nsub + 16 * k;
            int cur = yr[t];
            nacc += xn[t * LL + cur];
            if (t < TT - 1) nacc += trans[cur * LL + yr[t + 1]];
        }
        if (nsub == 0)  nacc += st[yr[0]];
        if (nsub == 15) nacc += et[yr[TT - 1]];
        sNum[nrow][nsub] = nacc;
    }
    __syncthreads();

    // ---- t = 0 init: V0 = exp(st + x0), staged 16 thr/row x 8 cols ----
    {
        const int prow = tid >> 4;
        const int pc   = (tid & 15) * 8;
        const float* xr = x + ((size_t)(gb + prow) * TT) * LL + pc;
        float4 a = *(const float4*)(xr);
        float4 b = *(const float4*)(xr + 4);
        uint4 v;
        v.x = packbf2(__expf(sSt[pc + 0] + a.x), __expf(sSt[pc + 1] + a.y));
        v.y = packbf2(__expf(sSt[pc + 2] + a.z), __expf(sSt[pc + 3] + a.w));
        v.z = packbf2(__expf(sSt[pc + 4] + b.x), __expf(sSt[pc + 5] + b.y));
        v.w = packbf2(__expf(sSt[pc + 6] + b.z), __expf(sSt[pc + 7] + b.w));
        *(uint4*)&sV[0][prow * SVS + pc] = v;
    }

    // ---- emission prefetch pointers (fragment coords, 2 steps ahead) ----
    const float* xrA = x + ((size_t)(gb + rQ)     * TT) * LL + c0;
    const float* xrB = x + ((size_t)(gb + rQ + 8) * TT) * LL + c0;
    float2 xpf[2][4];   // [t&1][h*2+nt]
    #pragma unroll
    for (int nt = 0; nt < 2; nt++) {
        xpf[1][0 + nt] = *(const float2*)(xrA + LL + nt * 8);
        xpf[1][2 + nt] = *(const float2*)(xrB + LL + nt * 8);
        xpf[0][0 + nt] = *(const float2*)(xrA + 2 * LL + nt * 8);
        xpf[0][2 + nt] = *(const float2*)(xrB + 2 * LL + nt * 8);
    }

    // ---- per-lane ldmatrix / STS offsets (bytes) ----
    const int rowL = lane & 15;
    const int sel8 = (lane >> 4) * 8;
    const uint32_t Aoff = (rowL * SVS + sel8) * 2;
    uint32_t Voff[2];
    #pragma unroll
    for (int h = 0; h < 2; h++)
        Voff[h] = ((h * 8 + rQ) * SVS + 16 * w + cQ2) * 2;

    const uint32_t svb[2] = { smem_u32(&sV[0][0]), smem_u32(&sV[1][0]) };

    float val[2][4];

    for (int t = 1; t < TT; t++) {
        const int rd = (t - 1) & 1, wr = t & 1;
        const int b  = t & 1;
        __syncthreads();

        // A fragments (all 8 k-tiles)
        uint32_t Af[8][4];
        #pragma unroll
        for (int ks = 0; ks < 8; ks++)
            ldsm4(Af[ks], svb[rd] + Aoff + ks * 32);

        // emissions for this step from prefetch buffer
        float P[2][4];
        #pragma unroll
        for (int h = 0; h < 2; h++)
            #pragma unroll
            for (int nt = 0; nt < 2; nt++) {
                float2 xv = xpf[b][h * 2 + nt];
                P[nt][2 * h]     = __expf(xv.x);
                P[nt][2 * h + 1] = __expf(xv.y);
            }
        // refill buffer for t+2
        if (t + 2 < TT) {
            #pragma unroll
            for (int nt = 0; nt < 2; nt++) {
                xpf[b][0 + nt] = *(const float2*)(xrA + (size_t)(t + 2) * LL + nt * 8);
                xpf[b][2 + nt] = *(const float2*)(xrB + (size_t)(t + 2) * LL + nt * 8);
            }
        }

        // split-K GEMM
        float D0[2][4] = {{0.f,0.f,0.f,0.f},{0.f,0.f,0.f,0.f}};
        float D1[2][4] = {{0.f,0.f,0.f,0.f},{0.f,0.f,0.f,0.f}};
        #pragma unroll
        for (int ks = 0; ks < 4; ks++) {
            mma16816(D0[0], Af[ks],     Bf[ks][0]);
            mma16816(D0[1], Af[ks],     Bf[ks][1]);
            mma16816(D1[0], Af[ks + 4], Bf[ks + 4][0]);
            mma16816(D1[1], Af[ks + 4], Bf[ks + 4][1]);
        }
        #pragma unroll
        for (int nt = 0; nt < 2; nt++)
            #pragma unroll
            for (int k = 0; k < 4; k++)
                val[nt][k] = (D0[nt][k] + D1[nt][k]) * P[nt][k];

        // per-row renorm every 8 steps
        if ((t & 7) == 0) {
            #pragma unroll
            for (int h = 0; h < 2; h++) {
                float m = fmaxf(fmaxf(val[0][2*h], val[0][2*h+1]),
                                fmaxf(val[1][2*h], val[1][2*h+1]));
                m = fmaxf(m, __shfl_xor_sync(0xffffffffu, m, 1));
                m = fmaxf(m, __shfl_xor_sync(0xffffffffu, m, 2));
                if ((lane & 3) == 0) sRed[w][h * 8 + rQ] = m;
            }
            __syncthreads();
            #pragma unroll
            for (int h = 0; h < 2; h++) {
                int row = h * 8 + rQ;
                float m = sRed[0][row];
                #pragma unroll
                for (int w2 = 1; w2 < 8; w2++) m = fmaxf(m, sRed[w2][row]);
                float inv = __fdividef(1.0f, m);
                val[0][2*h] *= inv; val[0][2*h+1] *= inv;
                val[1][2*h] *= inv; val[1][2*h+1] *= inv;
                if (w == 0 && (lane & 3) == 0) sS[row] += __logf(m);
            }
        }

        if (t < TT - 1) {
            char* vb = (char*)&sV[wr][0];
            #pragma unroll
            for (int h = 0; h < 2; h++) {
                *(uint32_t*)(vb + Voff[h])      = packbf2(val[0][2*h], val[0][2*h+1]);
                *(uint32_t*)(vb + Voff[h] + 16) = packbf2(val[1][2*h], val[1][2*h+1]);
            }
        }
    }

    // ---- epilogue: Z per row, then out = num - (slog + log Z) ----
    #pragma unroll
    for (int h = 0; h < 2; h++) {
        float z = val[0][2*h] * eet[0][0] + val[0][2*h+1] * eet[0][1]
                + val[1][2*h] * eet[1][0] + val[1][2*h+1] * eet[1][1];
        z += __shfl_xor_sync(0xffffffffu, z, 1);
        z += __shfl_xor_sync(0xffffffffu, z, 2);
        if ((lane & 3) == 0) sRed[w][h * 8 + rQ] = z;
    }
    __syncthreads();
    if (tid < MT) {
        float Z = 0.0f;
        #pragma unroll
        for (int w2 = 0; w2 < 8; w2++) Z += sRed[w2][tid];
        float num = 0.0f;
        #pragma unroll
        for (int k = 0; k < 16; k++) num += sNum[tid][k];
        out[gb + tid] = num - (sS[tid] + __logf(Z));
    }
}

// -------------------------------------------------------------------------
extern "C" void kernel_launch(void* const* d_in, const int* in_sizes, int n_in,
                              void* d_out, int out_size)
{
    const float* x     = (const float*)d_in[0];
    const float* trans = (const float*)d_in[1];
    const float* st    = (const float*)d_in[2];
    const float* et    = (const float*)d_in[3];
    const int*   y     = (const int*)  d_in[4];
    float*       out   = (float*)d_out;

    crf_fwd_kernel<<<NCF, 256>>>(x, trans, st, et, y, out);
}

// round 16
// speedup vs baseline: 2.3855x; 1.1604x over previous
#include <cuda_runtime.h>
#include <cuda_bf16.h>
#include <math.h>
#include <stdint.h>

#define BB 2048
#define TT 80
#define LL 128
#define MT 16             // batch rows per CTA
#define NCF 128           // grid
#define SVS 136           // padded V row stride in bf16 elems

// ---- helpers ----
__device__ __forceinline__ uint32_t packbf2(float lo, float hi) {
    uint32_t r;
    asm("cvt.rn.satfinite.bf16x2.f32 %0, %1, %2;" : "=r"(r) : "f"(hi), "f"(lo));
    return r;
}
__device__ __forceinline__ uint32_t smem_u32(const void* p) {
    uint32_t a;
    asm("{ .reg .u64 t; cvta.to.shared.u64 t, %1; cvt.u32.u64 %0, t; }" : "=r"(a) : "l"(p));
    return a;
}
__device__ __forceinline__ void ldsm4(uint32_t r[4], uint32_t addr) {
    asm volatile("ldmatrix.sync.aligned.m8n8.x4.shared.b16 {%0,%1,%2,%3}, [%4];"
        : "=r"(r[0]), "=r"(r[1]), "=r"(r[2]), "=r"(r[3]) : "r"(addr));
}
__device__ __forceinline__ void mma16816(float d[4], const uint32_t a[4], const uint32_t b[2]) {
    asm volatile("mma.sync.aligned.m16n8k16.row.col.f32.bf16.bf16.f32 "
        "{%0,%1,%2,%3}, {%4,%5,%6,%7}, {%8,%9}, {%0,%1,%2,%3};"
        : "+f"(d[0]), "+f"(d[1]), "+f"(d[2]), "+f"(d[3])
        : "r"(a[0]), "r"(a[1]), "r"(a[2]), "r"(a[3]), "r"(b[0]), "r"(b[1]));
}

// -------------------------------------------------------------------------
// Fused CRF kernel (R8/R15 structure). 128 CTAs x 256 thr (8 warps).
// R16 delta: per-n-tile interleaved tail on non-renorm steps (epilogue +
// pack + STS of n-tile 0 issue before n-tile 1's MMAs) — order-only,
// bitwise-identical numerics, shrinks D live ranges.
// Known noise: container clock floats ~25-30% between sessions; judge by
// ratio metrics.
// -------------------------------------------------------------------------
__global__ void __launch_bounds__(256, 1) crf_fwd_kernel(
    const float* __restrict__ x,
    const float* __restrict__ trans,
    const float* __restrict__ st,
    const float* __restrict__ et,
    const int*   __restrict__ y,
    float*       __restrict__ out)
{
    __shared__ __align__(16) __nv_bfloat16 sV[2][MT * SVS];
    __shared__ float sSt[LL];
    __shared__ float sRed[8][MT];
    __shared__ float sS[MT];
    __shared__ float sNum[MT][16];

    const int tid  = threadIdx.x;
    const int w    = tid >> 5;
    const int lane = tid & 31;
    const int gb   = blockIdx.x * MT;

    // ---- static B fragments: exp(trans)[k][n] in mma col-B layout ----
    uint32_t Bf[8][2][2];
    {
        const int jn = 16 * w + (lane >> 2);
        const int kb = (lane & 3) * 2;
        #pragma unroll
        for (int ks = 0; ks < 8; ks++)
            #pragma unroll
            for (int nt = 0; nt < 2; nt++) {
                int j  = jn + nt * 8;
                int k0 = ks * 16 + kb;
                Bf[ks][nt][0] = packbf2(__expf(trans[k0 * LL + j]),
                                        __expf(trans[(k0 + 1) * LL + j]));
                Bf[ks][nt][1] = packbf2(__expf(trans[(k0 + 8) * LL + j]),
                                        __expf(trans[(k0 + 9) * LL + j]));
            }
    }
    const int rQ  = lane >> 2;
    const int cQ2 = (lane & 3) * 2;
    const int c0  = 16 * w + cQ2;
    float eet[2][2];
    eet[0][0] = __expf(et[c0]);     eet[0][1] = __expf(et[c0 + 1]);
    eet[1][0] = __expf(et[c0 + 8]); eet[1][1] = __expf(et[c0 + 9]);
    if (tid < LL) sSt[tid] = st[tid];
    if (tid < MT) sS[tid] = 0.0f;

    // ---- gold-path numerator: 16 threads per row, 5 time-chunks each ----
    {
        const int nrow = tid >> 4, nsub = tid & 15;
        const int*   yr = y + (gb + nrow) * TT;
        const float* xn = x + (size_t)(gb + nrow) * TT * LL;
        float nacc = 0.0f;
        #pragma unroll
        for (int k = 0; k < 5; k++) {
            int t = nsub + 16 * k;
            int cur = yr[t];
            nacc += xn[t * LL + cur];
            if (t < TT - 1) nacc += trans[cur * LL + yr[t + 1]];
        }
        if (nsub == 0)  nacc += st[yr[0]];
        if (nsub == 15) nacc += et[yr[TT - 1]];
        sNum[nrow][nsub] = nacc;
    }
    __syncthreads();

    // ---- t = 0 init: V0 = exp(st + x0), staged 16 thr/row x 8 cols ----
    {
        const int prow = tid >> 4;
        const int pc   = (tid & 15) * 8;
        const float* xr = x + ((size_t)(gb + prow) * TT) * LL + pc;
        float4 a = *(const float4*)(xr);
        float4 b = *(const float4*)(xr + 4);
        uint4 v;
        v.x = packbf2(__expf(sSt[pc + 0] + a.x), __expf(sSt[pc + 1] + a.y));
        v.y = packbf2(__expf(sSt[pc + 2] + a.z), __expf(sSt[pc + 3] + a.w));
        v.z = packbf2(__expf(sSt[pc + 4] + b.x), __expf(sSt[pc + 5] + b.y));
        v.w = packbf2(__expf(sSt[pc + 6] + b.z), __expf(sSt[pc + 7] + b.w));
        *(uint4*)&sV[0][prow * SVS + pc] = v;
    }

    // ---- emission prefetch pointers (fragment coords, 2 steps ahead) ----
    const float* xrA = x + ((size_t)(gb + rQ)     * TT) * LL + c0;
    const float* xrB = x + ((size_t)(gb + rQ + 8) * TT) * LL + c0;
    float2 xpf[2][4];   // [t&1][h*2+nt]
    #pragma unroll
    for (int nt = 0; nt < 2; nt++) {
        xpf[1][0 + nt] = *(const float2*)(xrA + LL + nt * 8);
        xpf[1][2 + nt] = *(const float2*)(xrB + LL + nt * 8);
        xpf[0][0 + nt] = *(const float2*)(xrA + 2 * LL + nt * 8);
        xpf[0][2 + nt] = *(const float2*)(xrB + 2 * LL + nt * 8);
    }

    // ---- per-lane ldmatrix / STS offsets (bytes) ----
    const int rowL = lane & 15;
    const int sel8 = (lane >> 4) * 8;
    const uint32_t Aoff = (rowL * SVS + sel8) * 2;
    uint32_t Voff[2];
    #pragma unroll
    for (int h = 0; h < 2; h++)
        Voff[h] = ((h * 8 + rQ) * SVS + 16 * w + cQ2) * 2;

    const uint32_t svb[2] = { smem_u32(&sV[0][0]), smem_u32(&sV[1][0]) };

    float val[2][4];

    for (int t = 1; t < TT; t++) {
        const int rd = (t - 1) & 1, wr = t & 1;
        const int b  = t & 1;
        __syncthreads();

        // A fragments (all 8 k-tiles)
        uint32_t Af[8][4];
        #pragma unroll
        for (int ks = 0; ks < 8; ks++)
            ldsm4(Af[ks], svb[rd] + Aoff + ks * 32);

        // emissions for this step from prefetch buffer
        float P[2][4];
        #pragma unroll
        for (int h = 0; h < 2; h++)
            #pragma unroll
            for (int nt = 0; nt < 2; nt++) {
                float2 xv = xpf[b][h * 2 + nt];
                P[nt][2 * h]     = __expf(xv.x);
                P[nt][2 * h + 1] = __expf(xv.y);
            }
        // refill buffer for t+2
        if (t + 2 < TT) {
            #pragma unroll
            for (int nt = 0; nt < 2; nt++) {
                xpf[b][0 + nt] = *(const float2*)(xrA + (size_t)(t + 2) * LL + nt * 8);
                xpf[b][2 + nt] = *(const float2*)(xrB + (size_t)(t + 2) * LL + nt * 8);
            }
        }

        if ((t & 7) != 0) {
            // ---- fast path (70/79 steps): per-n-tile interleaved tail ----
            #pragma unroll
            for (int nt = 0; nt < 2; nt++) {
                float D0[4] = {0.f, 0.f, 0.f, 0.f};
                float D1[4] = {0.f, 0.f, 0.f, 0.f};
                #pragma unroll
                for (int ks = 0; ks < 4; ks++) {
                    mma16816(D0, Af[ks],     Bf[ks][nt]);
                    mma16816(D1, Af[ks + 4], Bf[ks + 4][nt]);
                }
                #pragma unroll
                for (int k = 0; k < 4; k++)
                    val[nt][k] = (D0[k] + D1[k]) * P[nt][k];
                if (t < TT - 1) {
                    char* vb = (char*)&sV[wr][0];
                    *(uint32_t*)(vb + Voff[0] + nt * 16) = packbf2(val[nt][0], val[nt][1]);
                    *(uint32_t*)(vb + Voff[1] + nt * 16) = packbf2(val[nt][2], val[nt][3]);
                }
            }
        } else {
            // ---- renorm path (9/79 steps): combined, as R15 ----
            float D0[2][4] = {{0.f,0.f,0.f,0.f},{0.f,0.f,0.f,0.f}};
            float D1[2][4] = {{0.f,0.f,0.f,0.f},{0.f,0.f,0.f,0.f}};
            #pragma unroll
            for (int ks = 0; ks < 4; ks++) {
                mma16816(D0[0], Af[ks],     Bf[ks][0]);
                mma16816(D0[1], Af[ks],     Bf[ks][1]);
                mma16816(D1[0], Af[ks + 4], Bf[ks + 4][0]);
                mma16816(D1[1], Af[ks + 4], Bf[ks + 4][1]);
            }
            #pragma unroll
            for (int nt = 0; nt < 2; nt++)
                #pragma unroll
                for (int k = 0; k < 4; k++)
                    val[nt][k] = (D0[nt][k] + D1[nt][k]) * P[nt][k];

            #pragma unroll
            for (int h = 0; h < 2; h++) {
                float m = fmaxf(fmaxf(val[0][2*h], val[0][2*h+1]),
                                fmaxf(val[1][2*h], val[1][2*h+1]));
                m = fmaxf(m, __shfl_xor_sync(0xffffffffu, m, 1));
                m = fmaxf(m, __shfl_xor_sync(0xffffffffu, m, 2));
                if ((lane & 3) == 0) sRed[w][h * 8 + rQ] = m;
            }
            __syncthreads();
            #pragma unroll
            for (int h = 0; h < 2; h++) {
                int row = h * 8 + rQ;
                float m = sRed[0][row];
                #pragma unroll
                for (int w2 = 1; w2 < 8; w2++) m = fmaxf(m, sRed[w2][row]);
                float inv = __fdividef(1.0f, m);
                val[0][2*h] *= inv; val[0][2*h+1] *= inv;
                val[1][2*h] *= inv; val[1][2*h+1] *= inv;
                if (w == 0 && (lane & 3) == 0) sS[row] += __logf(m);
            }
            if (t < TT - 1) {
                char* vb = (char*)&sV[wr][0];
                #pragma unroll
                for (int h = 0; h < 2; h++) {
                    *(uint32_t*)(vb + Voff[h])      = packbf2(val[0][2*h], val[0][2*h+1]);
                    *(uint32_t*)(vb + Voff[h] + 16) = packbf2(val[1][2*h], val[1][2*h+1]);
                }
            }
        }
    }

    // ---- epilogue: Z per row, then out = num - (slog + log Z) ----
    #pragma unroll
    for (int h = 0; h < 2; h++) {
        float z = val[0][2*h] * eet[0][0] + val[0][2*h+1] * eet[0][1]
                + val[1][2*h] * eet[1][0] + val[1][2*h+1] * eet[1][1];
        z += __shfl_xor_sync(0xffffffffu, z, 1);
        z += __shfl_xor_sync(0xffffffffu, z, 2);
        if ((lane & 3) == 0) sRed[w][h * 8 + rQ] = z;
    }
    __syncthreads();
    if (tid < MT) {
        float Z = 0.0f;
        #pragma unroll
        for (int w2 = 0; w2 < 8; w2++) Z += sRed[w2][tid];
        float num = 0.0f;
        #pragma unroll
        for (int k = 0; k < 16; k++) num += sNum[tid][k];
        out[gb + tid] = num - (sS[tid] + __logf(Z));
    }
}

// -------------------------------------------------------------------------
extern "C" void kernel_launch(void* const* d_in, const int* in_sizes, int n_in,
                              void* d_out, int out_size)
{
    const float* x     = (const float*)d_in[0];
    const float* trans = (const float*)d_in[1];
    const float* st    = (const float*)d_in[2];
    const float* et    = (const float*)d_in[3];
    const int*   y     = (const int*)  d_in[4];
    float*       out   = (float*)d_out;

    crf_fwd_kernel<<<NCF, 256>>>(x, trans, st, et, y, out);
}

// round 17
// speedup vs baseline: 2.8589x; 1.1984x over previous
#include <cuda_runtime.h>
#include <cuda_bf16.h>
#include <math.h>
#include <stdint.h>

#define BB 2048
#define TT 80
#define LL 128
#define MT 16             // batch rows per CTA
#define NCF 128           // grid
#define SVS 136           // padded V row stride in bf16 elems
#define TS 39             // steps per chain (alpha: t=1..39; beta: t=78..40)

// ---- helpers ----
__device__ __forceinline__ uint32_t packbf2(float lo, float hi) {
    uint32_t r;
    asm("cvt.rn.satfinite.bf16x2.f32 %0, %1, %2;" : "=r"(r) : "f"(hi), "f"(lo));
    return r;
}
__device__ __forceinline__ float bf_lo(uint32_t w) { return __uint_as_float(w << 16); }
__device__ __forceinline__ float bf_hi(uint32_t w) { return __uint_as_float(w & 0xFFFF0000u); }
__device__ __forceinline__ uint32_t smem_u32(const void* p) {
    uint32_t a;
    asm("{ .reg .u64 t; cvta.to.shared.u64 t, %1; cvt.u32.u64 %0, t; }" : "=r"(a) : "l"(p));
    return a;
}
__device__ __forceinline__ void ldsm4(uint32_t r[4], uint32_t addr) {
    asm volatile("ldmatrix.sync.aligned.m8n8.x4.shared.b16 {%0,%1,%2,%3}, [%4];"
        : "=r"(r[0]), "=r"(r[1]), "=r"(r[2]), "=r"(r[3]) : "r"(addr));
}
__device__ __forceinline__ void mma16816(float d[4], const uint32_t a[4], const uint32_t b[2]) {
    asm volatile("mma.sync.aligned.m16n8k16.row.col.f32.bf16.bf16.f32 "
        "{%0,%1,%2,%3}, {%4,%5,%6,%7}, {%8,%9}, {%0,%1,%2,%3};"
        : "+f"(d[0]), "+f"(d[1]), "+f"(d[2]), "+f"(d[3])
        : "r"(a[0]), "r"(a[1]), "r"(a[2]), "r"(a[3]), "r"(b[0]), "r"(b[1]));
}

// -------------------------------------------------------------------------
// Fused CRF kernel, forward+backward split (chain length 79 -> 40).
//   alpha_t = (alpha_{t-1} E) o p_t            t = 1..39
//   g_t     = p_t o (g_{t+1} E^T)              t = 78..40,  g_79 = p_79 o e^et
//   Z       = (alpha_39 E) . g_40              (bridge GEMM + dot)
// 128 CTAs x 256 thr (8 warps). Warp w owns n-slice [16w,16w+16) for BOTH
// chains. Bfa = exp(trans), Bfb = exp(trans)^T in regs. Both V buffers
// double-buffered in SMEM; per-chain renorm every 8 steps.
// -------------------------------------------------------------------------
__global__ void __launch_bounds__(256, 1) crf_fwd_kernel(
    const float* __restrict__ x,
    const float* __restrict__ trans,
    const float* __restrict__ st,
    const float* __restrict__ et,
    const int*   __restrict__ y,
    float*       __restrict__ out)
{
    __shared__ __align__(16) __nv_bfloat16 sVa[2][MT * SVS];
    __shared__ __align__(16) __nv_bfloat16 sVb[2][MT * SVS];
    __shared__ float sSt[LL], sEt[LL];
    __shared__ float sRedA[8][MT], sRedB[8][MT];
    __shared__ float sSA[MT], sSB[MT];
    __shared__ float sNum[MT][16];

    const int tid  = threadIdx.x;
    const int w    = tid >> 5;
    const int lane = tid & 31;
    const int gb   = blockIdx.x * MT;

    // ---- B fragments: Bfa = exp(trans)[k][n]; Bfb = exp(trans)[n][k] ----
    uint32_t Bfa[8][2][2], Bfb[8][2][2];
    {
        const int jn = 16 * w + (lane >> 2);
        const int kb = (lane & 3) * 2;
        #pragma unroll
        for (int ks = 0; ks < 8; ks++)
            #pragma unroll
            for (int nt = 0; nt < 2; nt++) {
                int j  = jn + nt * 8;
                int k0 = ks * 16 + kb;
                Bfa[ks][nt][0] = packbf2(__expf(trans[k0 * LL + j]),
                                         __expf(trans[(k0 + 1) * LL + j]));
                Bfa[ks][nt][1] = packbf2(__expf(trans[(k0 + 8) * LL + j]),
                                         __expf(trans[(k0 + 9) * LL + j]));
                Bfb[ks][nt][0] = packbf2(__expf(trans[j * LL + k0]),
                                         __expf(trans[j * LL + k0 + 1]));
                Bfb[ks][nt][1] = packbf2(__expf(trans[j * LL + k0 + 8]),
                                         __expf(trans[j * LL + k0 + 9]));
            }
    }
    const int rQ  = lane >> 2;
    const int cQ2 = (lane & 3) * 2;
    const int c0  = 16 * w + cQ2;
    if (tid < LL) { sSt[tid] = st[tid]; sEt[tid] = et[tid]; }
    if (tid < MT) { sSA[tid] = 0.0f; sSB[tid] = 0.0f; }

    // ---- gold-path numerator: 16 threads per row, 5 time-chunks each ----
    {
        const int nrow = tid >> 4, nsub = tid & 15;
        const int*   yr = y + (gb + nrow) * TT;
        const float* xn = x + (size_t)(gb + nrow) * TT * LL;
        float nacc = 0.0f;
        #pragma unroll
        for (int k = 0; k < 5; k++) {
            int t = nsub + 16 * k;
            int cur = yr[t];
            nacc += xn[t * LL + cur];
            if (t < TT - 1) nacc += trans[cur * LL + yr[t + 1]];
        }
        if (nsub == 0)  nacc += st[yr[0]];
        if (nsub == 15) nacc += et[yr[TT - 1]];
        sNum[nrow][nsub] = nacc;
    }
    __syncthreads();

    // ---- init: alpha_0 = exp(st + x0);  g_79 = exp(x79 + et) ----
    {
        const int prow = tid >> 4;
        const int pc   = (tid & 15) * 8;
        const float* xr0 = x + ((size_t)(gb + prow) * TT) * LL + pc;
        const float* xr9 = x + ((size_t)(gb + prow) * TT + (TT - 1)) * LL + pc;
        float4 a = *(const float4*)(xr0);
        float4 b = *(const float4*)(xr0 + 4);
        uint4 v;
        v.x = packbf2(__expf(sSt[pc + 0] + a.x), __expf(sSt[pc + 1] + a.y));
        v.y = packbf2(__expf(sSt[pc + 2] + a.z), __expf(sSt[pc + 3] + a.w));
        v.z = packbf2(__expf(sSt[pc + 4] + b.x), __expf(sSt[pc + 5] + b.y));
        v.w = packbf2(__expf(sSt[pc + 6] + b.z), __expf(sSt[pc + 7] + b.w));
        *(uint4*)&sVa[0][prow * SVS + pc] = v;
        float4 c = *(const float4*)(xr9);
        float4 d = *(const float4*)(xr9 + 4);
        uint4 g;
        g.x = packbf2(__expf(c.x + sEt[pc + 0]), __expf(c.y + sEt[pc + 1]));
        g.y = packbf2(__expf(c.z + sEt[pc + 2]), __expf(c.w + sEt[pc + 3]));
        g.z = packbf2(__expf(d.x + sEt[pc + 4]), __expf(d.y + sEt[pc + 5]));
        g.w = packbf2(__expf(d.z + sEt[pc + 6]), __expf(d.w + sEt[pc + 7]));
        *(uint4*)&sVb[0][prow * SVS + pc] = g;
    }

    // ---- emission prefetch (2 iterations ahead, both chains) ----
    const float* xrA = x + ((size_t)(gb + rQ)     * TT) * LL + c0;
    const float* xrB = x + ((size_t)(gb + rQ + 8) * TT) * LL + c0;
    float2 xpfA[2][4], xpfB[2][4];   // [s&1][h*2+nt]; alpha t=s, beta t=79-s
    #pragma unroll
    for (int nt = 0; nt < 2; nt++) {
        xpfA[1][0 + nt] = *(const float2*)(xrA + 1 * LL + nt * 8);
        xpfA[1][2 + nt] = *(const float2*)(xrB + 1 * LL + nt * 8);
        xpfA[0][0 + nt] = *(const float2*)(xrA + 2 * LL + nt * 8);
        xpfA[0][2 + nt] = *(const float2*)(xrB + 2 * LL + nt * 8);
        xpfB[1][0 + nt] = *(const float2*)(xrA + 78 * LL + nt * 8);
        xpfB[1][2 + nt] = *(const float2*)(xrB + 78 * LL + nt * 8);
        xpfB[0][0 + nt] = *(const float2*)(xrA + 77 * LL + nt * 8);
        xpfB[0][2 + nt] = *(const float2*)(xrB + 77 * LL + nt * 8);
    }

    // ---- per-lane ldmatrix / STS offsets (bytes) ----
    const int rowL = lane & 15;
    const int sel8 = (lane >> 4) * 8;
    const uint32_t Aoff = (rowL * SVS + sel8) * 2;
    uint32_t Voff[2];
    #pragma unroll
    for (int h = 0; h < 2; h++)
        Voff[h] = ((h * 8 + rQ) * SVS + 16 * w + cQ2) * 2;

    const uint32_t svA[2] = { smem_u32(&sVa[0][0]), smem_u32(&sVa[1][0]) };
    const uint32_t svB[2] = { smem_u32(&sVb[0][0]), smem_u32(&sVb[1][0]) };

    float valA[2][4], valB[2][4];

    for (int s = 1; s <= TS; s++) {
        const int rd = (s - 1) & 1, wr = s & 1, b = s & 1;
        __syncthreads();

        // ---- alpha chain step (t = s) ----
        {
            uint32_t Af[8][4];
            #pragma unroll
            for (int ks = 0; ks < 8; ks++)
                ldsm4(Af[ks], svA[rd] + Aoff + ks * 32);
            float P[2][4];
            #pragma unroll
            for (int h = 0; h < 2; h++)
                #pragma unroll
                for (int nt = 0; nt < 2; nt++) {
                    float2 xv = xpfA[b][h * 2 + nt];
                    P[nt][2 * h]     = __expf(xv.x);
                    P[nt][2 * h + 1] = __expf(xv.y);
                }
            float D0[2][4] = {{0.f,0.f,0.f,0.f},{0.f,0.f,0.f,0.f}};
            float D1[2][4] = {{0.f,0.f,0.f,0.f},{0.f,0.f,0.f,0.f}};
            #pragma unroll
            for (int ks = 0; ks < 4; ks++) {
                mma16816(D0[0], Af[ks],     Bfa[ks][0]);
                mma16816(D0[1], Af[ks],     Bfa[ks][1]);
                mma16816(D1[0], Af[ks + 4], Bfa[ks + 4][0]);
                mma16816(D1[1], Af[ks + 4], Bfa[ks + 4][1]);
            }
            #pragma unroll
            for (int nt = 0; nt < 2; nt++)
                #pragma unroll
                for (int k = 0; k < 4; k++)
                    valA[nt][k] = (D0[nt][k] + D1[nt][k]) * P[nt][k];
        }

        // refill prefetch for iteration s+2 (alpha t=s+2, beta t=77-s)
        if (s + 2 <= TS) {
            #pragma unroll
            for (int nt = 0; nt < 2; nt++) {
                xpfA[b][0 + nt] = *(const float2*)(xrA + (size_t)(s + 2) * LL + nt * 8);
                xpfA[b][2 + nt] = *(const float2*)(xrB + (size_t)(s + 2) * LL + nt * 8);
                xpfB[b][0 + nt] = *(const float2*)(xrA + (size_t)(77 - s) * LL + nt * 8);
                xpfB[b][2 + nt] = *(const float2*)(xrB + (size_t)(77 - s) * LL + nt * 8);
            }
        }

        // ---- beta chain step (t = 79 - s) ----
        {
            uint32_t Af[8][4];
            #pragma unroll
            for (int ks = 0; ks < 8; ks++)
                ldsm4(Af[ks], svB[rd] + Aoff + ks * 32);
            float P[2][4];
            #pragma unroll
            for (int h = 0; h < 2; h++)
                #pragma unroll
                for (int nt = 0; nt < 2; nt++) {
                    float2 xv = xpfB[b][h * 2 + nt];
                    P[nt][2 * h]     = __expf(xv.x);
                    P[nt][2 * h + 1] = __expf(xv.y);
                }
            float D0[2][4] = {{0.f,0.f,0.f,0.f},{0.f,0.f,0.f,0.f}};
            float D1[2][4] = {{0.f,0.f,0.f,0.f},{0.f,0.f,0.f,0.f}};
            #pragma unroll
            for (int ks = 0; ks < 4; ks++) {
                mma16816(D0[0], Af[ks],     Bfb[ks][0]);
                mma16816(D0[1], Af[ks],     Bfb[ks][1]);
                mma16816(D1[0], Af[ks + 4], Bfb[ks + 4][0]);
                mma16816(D1[1], Af[ks + 4], Bfb[ks + 4][1]);
            }
            #pragma unroll
            for (int nt = 0; nt < 2; nt++)
                #pragma unroll
                for (int k = 0; k < 4; k++)
                    valB[nt][k] = (D0[nt][k] + D1[nt][k]) * P[nt][k];
        }

        // ---- per-chain renorm every 8 steps ----
        if ((s & 7) == 0) {
            #pragma unroll
            for (int h = 0; h < 2; h++) {
                float mA = fmaxf(fmaxf(valA[0][2*h], valA[0][2*h+1]),
                                 fmaxf(valA[1][2*h], valA[1][2*h+1]));
                float mB = fmaxf(fmaxf(valB[0][2*h], valB[0][2*h+1]),
                                 fmaxf(valB[1][2*h], valB[1][2*h+1]));
                mA = fmaxf(mA, __shfl_xor_sync(0xffffffffu, mA, 1));
                mA = fmaxf(mA, __shfl_xor_sync(0xffffffffu, mA, 2));
                mB = fmaxf(mB, __shfl_xor_sync(0xffffffffu, mB, 1));
                mB = fmaxf(mB, __shfl_xor_sync(0xffffffffu, mB, 2));
                if ((lane & 3) == 0) {
                    sRedA[w][h * 8 + rQ] = mA;
                    sRedB[w][h * 8 + rQ] = mB;
                }
            }
            __syncthreads();
            #pragma unroll
            for (int h = 0; h < 2; h++) {
                int row = h * 8 + rQ;
                float mA = sRedA[0][row], mB = sRedB[0][row];
                #pragma unroll
                for (int w2 = 1; w2 < 8; w2++) {
                    mA = fmaxf(mA, sRedA[w2][row]);
                    mB = fmaxf(mB, sRedB[w2][row]);
                }
                float iA = __fdividef(1.0f, mA);
                float iB = __fdividef(1.0f, mB);
                valA[0][2*h] *= iA; valA[0][2*h+1] *= iA;
                valA[1][2*h] *= iA; valA[1][2*h+1] *= iA;
                valB[0][2*h] *= iB; valB[0][2*h+1] *= iB;
                valB[1][2*h] *= iB; valB[1][2*h+1] *= iB;
                if (w == 0 && (lane & 3) == 0) {
                    sSA[row] += __logf(mA);
                    sSB[row] += __logf(mB);
                }
            }
        }

        // ---- store both chains (always: bridge reads the s=39 buffers) ----
        {
            char* va = (char*)&sVa[wr][0];
            char* vb = (char*)&sVb[wr][0];
            #pragma unroll
            for (int h = 0; h < 2; h++) {
                *(uint32_t*)(va + Voff[h])      = packbf2(valA[0][2*h], valA[0][2*h+1]);
                *(uint32_t*)(va + Voff[h] + 16) = packbf2(valA[1][2*h], valA[1][2*h+1]);
                *(uint32_t*)(vb + Voff[h])      = packbf2(valB[0][2*h], valB[0][2*h+1]);
                *(uint32_t*)(vb + Voff[h] + 16) = packbf2(valB[1][2*h], valB[1][2*h+1]);
            }
        }
    }

    // ---- bridge: Z = (alpha_39 E) . g_40 ----
    __syncthreads();
    float z[2] = {0.0f, 0.0f};
    {
        const int fb = TS & 1;    // = 1
        uint32_t Af[8][4];
        #pragma unroll
        for (int ks = 0; ks < 8; ks++)
            ldsm4(Af[ks], svA[fb] + Aoff + ks * 32);
        float D0[2][4] = {{0.f,0.f,0.f,0.f},{0.f,0.f,0.f,0.f}};
        float D1[2][4] = {{0.f,0.f,0.f,0.f},{0.f,0.f,0.f,0.f}};
        #pragma unroll
        for (int ks = 0; ks < 4; ks++) {
            mma16816(D0[0], Af[ks],     Bfa[ks][0]);
            mma16816(D0[1], Af[ks],     Bfa[ks][1]);
            mma16816(D1[0], Af[ks + 4], Bfa[ks + 4][0]);
            mma16816(D1[1], Af[ks + 4], Bfa[ks + 4][1]);
        }
        const char* vb = (const char*)&sVb[fb][0];
        #pragma unroll
        for (int h = 0; h < 2; h++)
            #pragma unroll
            for (int nt = 0; nt < 2; nt++) {
                uint32_t gw = *(const uint32_t*)(vb + Voff[h] + nt * 16);
                z[h] += (D0[nt][2*h]   + D1[nt][2*h])   * bf_lo(gw)
                      + (D0[nt][2*h+1] + D1[nt][2*h+1]) * bf_hi(gw);
            }
    }
    #pragma unroll
    for (int h = 0; h < 2; h++) {
        z[h] += __shfl_xor_sync(0xffffffffu, z[h], 1);
        z[h] += __shfl_xor_sync(0xffffffffu, z[h], 2);
        if ((lane & 3) == 0) sRedA[w][h * 8 + rQ] = z[h];
    }
    __syncthreads();
    if (tid < MT) {
        float Z = 0.0f;
        #pragma unroll
        for (int w2 = 0; w2 < 8; w2++) Z += sRedA[w2][tid];
        float num = 0.0f;
        #pragma unroll
        for (int k = 0; k < 16; k++) num += sNum[tid][k];
        out[gb + tid] = num - (sSA[tid] + sSB[tid] + __logf(Z));
    }
}

// -------------------------------------------------------------------------
extern "C" void kernel_launch(void* const* d_in, const int* in_sizes, int n_in,
                              void* d_out, int out_size)
{
    const float* x     = (const float*)d_in[0];
    const float* trans = (const float*)d_in[1];
    const float* st    = (const float*)d_in[2];
    const float* et    = (const float*)d_in[3];
    const int*   y     = (const int*)  d_in[4];
    float*       out   = (float*)d_out;

    crf_fwd_kernel<<<NCF, 256>>>(x, trans, st, et, y, out);
}